// round 9
// baseline (speedup 1.0000x reference)
#include <cuda_runtime.h>
#include <cuda_bf16.h>
#include <cstdint>

// ---------------------------------------------------------------------------
// Compile-time normalization constants K(l,m) baked in as immediates:
//   K = sqrt((2l+1)/(4pi) * (l-m)!/(l+m)!),   times sqrt(2) for m != 0
// ---------------------------------------------------------------------------
namespace {

constexpr double csqrt(double x) {
    double g = x > 1.0 ? x : 1.0;
    for (int i = 0; i < 100; i++) g = 0.5 * (g + x / g);
    return g;
}
constexpr double dfact(int n) {
    double r = 1.0;
    for (int i = 2; i <= n; i++) r *= (double)i;
    return r;
}
constexpr double PI_D = 3.14159265358979323846;

struct KTab { float c[8][8]; };

constexpr KTab mk_ktab() {
    KTab t{};
    for (int l = 0; l < 8; l++)
        for (int m = 0; m <= l; m++) {
            double K = csqrt((2.0 * l + 1.0) / (4.0 * PI_D)
                             * dfact(l - m) / dfact(l + m));
            if (m > 0) K *= csqrt(2.0);
            t.c[l][m] = (float)K;
        }
    return t;
}

__device__ constexpr KTab g_Kc = mk_ktab();

} // namespace

// ---------------------------------------------------------------------------
// l-outer pipeline, 2 POINTS PER THREAD (block covers 512 points), 2-slot
// SMEM ring buffer (dynamic, 2 x 15*512 floats = 61.4 KB).
// Region l staged in slot (l&1) in output order: point pt (0..511), col j at
// pt*w + j  (lane stride w odd => conflict-free). Thread t stages pt=t and
// pt=t+256 (independent recurrence chains => 2-way ILP).
// After a barrier, thread 0 issues ONE cp.async.bulk (6..30 KB) and
// wait_group 1 guarantees the slot reused next time has drained.
// l = 0 is the constant Y00 (direct coalesced stores).
// ---------------------------------------------------------------------------
constexpr int TPB  = 256;
constexpr int PPB  = 512;                    // points per block
constexpr int SLOT_FLOATS = 15 * PPB;        // largest region (l=7)
constexpr int SMEM_BYTES  = 2 * SLOT_FLOATS * 4;   // 61440

__device__ __forceinline__ uint32_t smem_u32(const void* p) {
    uint32_t a;
    asm("{ .reg .u64 t; cvta.to.shared.u64 t, %1; cvt.u32.u64 %0, t; }"
        : "=r"(a) : "l"(p));
    return a;
}

__global__ __launch_bounds__(TPB, 3)
void sph_harm_kernel(const float* __restrict__ cos_theta,
                     const float* __restrict__ phi,
                     float* __restrict__ out,
                     int N)
{
    extern __shared__ float smb[];           // 2 slots

    const int t  = threadIdx.x;
    const long long bs = (long long)blockIdx.x * PPB;
    const int rows = (int)min((long long)PPB, (long long)N - bs);
    const bool full = (rows == PPB) && ((N & 3) == 0);

    // two points per thread: pt = t and pt = t + TPB
    int   n[2];
    float x[2], s[2], spv[2], cpv[2];
    #pragma unroll
    for (int q = 0; q < 2; q++) {
        n[q] = (int)bs + t + q * TPB;
        const int nc = (n[q] < N) ? n[q] : (N - 1);
        x[q] = cos_theta[nc];
        const float p = phi[nc];
        s[q] = sqrtf(fmaxf(1.0f - x[q] * x[q], 0.0f));
        __sincosf(p, &spv[q], &cpv[q]);
        if (n[q] < N) out[n[q]] = g_Kc.c[0][0];   // l = 0
    }

    // Recurrence state (fully unrolled -> registers).
    float Pp[2][8];     // P_{l-1}^m
    float Ppp[2][8];    // P_{l-2}^m
    float cmv[2][8], smv[2][8];
    #pragma unroll
    for (int q = 0; q < 2; q++) {
        Pp[q][0] = 1.0f;
        cmv[q][0] = 1.0f; smv[q][0] = 0.0f;
    }

    #pragma unroll
    for (int l = 1; l <= 7; l++) {
        const int w = 2 * l + 1;
        float* buf = smb + (l & 1) * SLOT_FLOATS;

        #pragma unroll
        for (int q = 0; q < 2; q++) {
            float Pl[8];
            #pragma unroll
            for (int m = 0; m <= l - 2; m++)
                Pl[m] = ((2.0f * l - 1.0f) * x[q] * Pp[q][m]
                         - (float)(l + m - 1) * Ppp[q][m])
                        * (1.0f / (float)(l - m));
            Pl[l - 1] = (2.0f * l - 1.0f) * x[q] * Pp[q][l - 1];
            Pl[l]     = -(2.0f * l - 1.0f) * s[q] * Pp[q][l - 1]; // C-S phase

            cmv[q][l] = cpv[q] * cmv[q][l - 1] - spv[q] * smv[q][l - 1];
            smv[q][l] = spv[q] * cmv[q][l - 1] + cpv[q] * smv[q][l - 1];

            // stage point (t + q*TPB) of region l
            {
                const int base = (t + q * TPB) * w;
                buf[base + l] = g_Kc.c[l][0] * Pl[0];
                #pragma unroll
                for (int m = 1; m <= l; m++) {
                    const float kp = g_Kc.c[l][m] * Pl[m];
                    buf[base + (l - m)] = kp * smv[q][m];
                    buf[base + (l + m)] = kp * cmv[q][m];
                }
            }

            // shift state
            #pragma unroll
            for (int m = 0; m <= l - 1; m++) Ppp[q][m] = Pp[q][m];
            #pragma unroll
            for (int m = 0; m <= l; m++)     Pp[q][m]  = Pl[m];
        }

        __syncthreads();                     // region staged (both halves)

        if (full) {
            if (t == 0) {
                asm volatile("fence.proxy.async.shared::cta;" ::: "memory");
                const uint32_t src = smem_u32(buf);
                float* dstp = out + (size_t)N * (size_t)(l * l)
                                  + (size_t)bs * (size_t)w;
                const uint32_t bytes = (uint32_t)(PPB * w * 4);
                asm volatile(
                    "cp.async.bulk.global.shared::cta.bulk_group [%0], [%1], %2;"
                    :: "l"(dstp), "r"(src), "r"(bytes) : "memory");
                asm volatile("cp.async.bulk.commit_group;" ::: "memory");
                // copy issued 2 regions ago (same slot) must have drained
                asm volatile("cp.async.bulk.wait_group 1;" ::: "memory");
            }
        } else {
            // tail / unaligned fallback (last block at N = 2M: rows = 128)
            float* dst = out + (size_t)N * (size_t)(l * l)
                             + (size_t)bs * (size_t)w;
            const int cnt = rows * w;
            for (int i = t; i < cnt; i += TPB)
                dst[i] = buf[i];
        }

        __syncthreads();                     // slot-reuse safety
    }

    if (full && t == 0)
        asm volatile("cp.async.bulk.wait_group 0;" ::: "memory");
}

extern "C" void kernel_launch(void* const* d_in, const int* in_sizes, int n_in,
                              void* d_out, int out_size)
{
    const float* cos_theta = (const float*)d_in[0];
    const float* phi       = (const float*)d_in[1];
    float* out             = (float*)d_out;
    const int N = in_sizes[0];

    cudaFuncSetAttribute(sph_harm_kernel,
                         cudaFuncAttributeMaxDynamicSharedMemorySize,
                         SMEM_BYTES);

    const int blocks = (N + PPB - 1) / PPB;
    sph_harm_kernel<<<blocks, TPB, SMEM_BYTES>>>(cos_theta, phi, out, N);
}

// round 10
// speedup vs baseline: 1.3098x; 1.3098x over previous
#include <cuda_runtime.h>
#include <cuda_bf16.h>
#include <cstdint>

// ---------------------------------------------------------------------------
// Compile-time normalization constants K(l,m) baked in as immediates:
//   K = sqrt((2l+1)/(4pi) * (l-m)!/(l+m)!),   times sqrt(2) for m != 0
// ---------------------------------------------------------------------------
namespace {

constexpr double csqrt(double x) {
    double g = x > 1.0 ? x : 1.0;
    for (int i = 0; i < 100; i++) g = 0.5 * (g + x / g);
    return g;
}
constexpr double dfact(int n) {
    double r = 1.0;
    for (int i = 2; i <= n; i++) r *= (double)i;
    return r;
}
constexpr double PI_D = 3.14159265358979323846;

struct KTab { float c[8][8]; };

constexpr KTab mk_ktab() {
    KTab t{};
    for (int l = 0; l < 8; l++)
        for (int m = 0; m <= l; m++) {
            double K = csqrt((2.0 * l + 1.0) / (4.0 * PI_D)
                             * dfact(l - m) / dfact(l + m));
            if (m > 0) K *= csqrt(2.0);
            t.c[l][m] = (float)K;
        }
    return t;
}

__device__ constexpr KTab g_Kc = mk_ktab();

} // namespace

// ---------------------------------------------------------------------------
// l-outer pipeline with a 3-slot SMEM ring buffer.
// Slot size = largest region (w=15): 15*TPB floats (15 KB); 3 slots = 46 KB.
// Region l staged in slot (l % 3) in output order (lane stride w odd =>
// conflict-free STS). Thread 0 then issues ONE cp.async.bulk shared->global
// (3..15 KB) and wait_group 2: the slot reused next at l+3 was issued three
// regions ago and has long drained, so the wait ~never blocks.
// __launch_bounds__(256,5): 5 blocks/SM (230.4 KB smem), ~40 warps.
// l = 0 is the constant Y00 (direct coalesced store).
// ---------------------------------------------------------------------------
constexpr int TPB = 256;
constexpr int SLOT_FLOATS = 15 * TPB;            // largest region (l=7)
constexpr int SMEM_BYTES  = 3 * SLOT_FLOATS * 4; // 46080

__device__ __forceinline__ uint32_t smem_u32(const void* p) {
    uint32_t a;
    asm("{ .reg .u64 t; cvta.to.shared.u64 t, %1; cvt.u32.u64 %0, t; }"
        : "=r"(a) : "l"(p));
    return a;
}

__global__ __launch_bounds__(TPB, 5)
void sph_harm_kernel(const float* __restrict__ cos_theta,
                     const float* __restrict__ phi,
                     float* __restrict__ out,
                     int N)
{
    extern __shared__ float smb[];               // 3 slots

    const int t  = threadIdx.x;
    const long long bs = (long long)blockIdx.x * TPB;
    const int n    = (int)bs + t;
    const int rows = (int)min((long long)TPB, (long long)N - bs);
    const bool full = (rows == TPB) && ((N & 3) == 0);

    const int nc = (n < N) ? n : (N - 1);

    const float x = cos_theta[nc];
    const float p = phi[nc];
    const float s = sqrtf(fmaxf(1.0f - x * x, 0.0f));

    float sp, cp;
    __sincosf(p, &sp, &cp);

    // l = 0 : Y00 is a constant.
    if (n < N) out[n] = g_Kc.c[0][0];

    // Recurrence state (fully unrolled -> registers).
    float Pp[8];    // P_{l-1}^m
    float Ppp[8];   // P_{l-2}^m
    float cmv[8], smv[8];
    Pp[0] = 1.0f;
    cmv[0] = 1.0f; smv[0] = 0.0f;

    #pragma unroll
    for (int l = 1; l <= 7; l++) {
        float Pl[8];
        #pragma unroll
        for (int m = 0; m <= l - 2; m++)
            Pl[m] = ((2.0f * l - 1.0f) * x * Pp[m]
                     - (float)(l + m - 1) * Ppp[m]) * (1.0f / (float)(l - m));
        Pl[l - 1] = (2.0f * l - 1.0f) * x * Pp[l - 1];
        Pl[l]     = -(2.0f * l - 1.0f) * s * Pp[l - 1];   // Condon-Shortley

        cmv[l] = cp * cmv[l - 1] - sp * smv[l - 1];
        smv[l] = sp * cmv[l - 1] + cp * smv[l - 1];

        const int w = 2 * l + 1;
        float* buf = smb + (l % 3) * SLOT_FLOATS;

        // stage region l (lane stride w odd -> conflict-free)
        {
            const int base = t * w;
            buf[base + l] = g_Kc.c[l][0] * Pl[0];
            #pragma unroll
            for (int m = 1; m <= l; m++) {
                const float kp = g_Kc.c[l][m] * Pl[m];
                buf[base + (l - m)] = kp * smv[m];
                buf[base + (l + m)] = kp * cmv[m];
            }
        }

        __syncthreads();                         // region staged

        if (full) {
            if (t == 0) {
                asm volatile("fence.proxy.async.shared::cta;" ::: "memory");
                const uint32_t src = smem_u32(buf);
                float* dstp = out + (size_t)N * (size_t)(l * l)
                                  + (size_t)bs * (size_t)w;
                const uint32_t bytes = (uint32_t)(TPB * w * 4);
                asm volatile(
                    "cp.async.bulk.global.shared::cta.bulk_group [%0], [%1], %2;"
                    :: "l"(dstp), "r"(src), "r"(bytes) : "memory");
                asm volatile("cp.async.bulk.commit_group;" ::: "memory");
                // keep <=2 groups in flight: the copy issued 3 regions ago
                // (the slot reused next) has certainly completed.
                asm volatile("cp.async.bulk.wait_group 2;" ::: "memory");
            }
        } else {
            // tail / unaligned fallback (not hit for N = 2M)
            float* dst = out + (size_t)N * (size_t)(l * l)
                             + (size_t)bs * (size_t)w;
            const int cnt = rows * w;
            for (int i = t; i < cnt; i += TPB)
                dst[i] = buf[i];
        }

        __syncthreads();                         // slot-reuse safety

        #pragma unroll
        for (int m = 0; m <= l - 1; m++) Ppp[m] = Pp[m];
        #pragma unroll
        for (int m = 0; m <= l; m++)     Pp[m]  = Pl[m];
    }

    if (full && t == 0)
        asm volatile("cp.async.bulk.wait_group 0;" ::: "memory");
}

extern "C" void kernel_launch(void* const* d_in, const int* in_sizes, int n_in,
                              void* d_out, int out_size)
{
    const float* cos_theta = (const float*)d_in[0];
    const float* phi       = (const float*)d_in[1];
    float* out             = (float*)d_out;
    const int N = in_sizes[0];

    cudaFuncSetAttribute(sph_harm_kernel,
                         cudaFuncAttributeMaxDynamicSharedMemorySize,
                         SMEM_BYTES);

    const int blocks = (N + TPB - 1) / TPB;
    sph_harm_kernel<<<blocks, TPB, SMEM_BYTES>>>(cos_theta, phi, out, N);
}